// round 5
// baseline (speedup 1.0000x reference)
#include <cuda_runtime.h>
#include <cooperative_groups.h>

namespace cg = cooperative_groups;

#define B_DIM 128
#define N_DIM 131072

constexpr int THREADS       = 256;
constexpr int CLUSTER       = 8;                       // CTAs per row (one cluster per row)
constexpr int ELEMS_PER_BLK = N_DIM / CLUSTER;         // 16384 elements (64 KB of w)
constexpr int VEC_PER_BLK   = ELEMS_PER_BLK / 4;       // 4096 float4
constexpr int VEC_PER_THR   = VEC_PER_BLK / THREADS;   // 16
constexpr int HALF_THR      = VEC_PER_THR / 2;         // 8 (split loop: reg pressure)
constexpr int SMEM_BYTES    = VEC_PER_BLK * 16;        // 65536 B dynamic smem

__device__ __forceinline__ float transition_likelihood(
    float x, float nz, float cterm, float ob, float pwv, float& w_out)
{
    // UNGM transition: x/2 + 25*x/(x^2+1) + 8*cos(1.2*t) + noise*sqrt(10)
    float mean = fmaf(x, 0.5f, 25.0f * __fdividef(x, fmaf(x, x, 1.0f))) + cterm;
    float np   = fmaf(nz, 3.16227766f, mean);
    float om   = np * np * 0.05f;                      // np^2 / 20
    float d    = ob - om;
    float lp   = fmaf(-0.5f * d, d, -0.9189385332f);   // -0.5*log(2*pi)
    w_out      = pwv * __expf(lp);
    return np;
}

__global__ void __launch_bounds__(THREADS, 3) __cluster_dims__(CLUSTER, 1, 1)
pf_cluster_kernel(const float* __restrict__ particles,
                  const float* __restrict__ pw,
                  const float* __restrict__ obs,
                  const float* __restrict__ noise,
                  const int*   __restrict__ tstep,
                  float* __restrict__ out_np,
                  float* __restrict__ out_w)
{
    extern __shared__ float4 w_s[];                    // [VEC_PER_BLK] = 64 KB
    __shared__ float red[THREADS / 32];
    __shared__ float s_partial;                        // this CTA's slice sum

    cg::cluster_group cluster = cg::this_cluster();

    const int  r    = blockIdx.y;                      // batch row
    const int  seg  = blockIdx.x;                      // slice within row (0..7)
    const long base = (long)r * N_DIM + (long)seg * ELEMS_PER_BLK;

    const float t     = (float)__ldg(tstep);
    const float cterm = 8.0f * cosf(1.2f * t);
    const float ob    = __ldg(obs + r);

    const float4* p4  = (const float4*)(particles + base);
    const float4* n4  = (const float4*)(noise + base);
    const float4* w4  = (const float4*)(pw + base);
    float4* onp4      = (float4*)(out_np + base);
    float4* ow4       = (float4*)(out_w + base);

    // ---- Phase 1: transition + likelihood; w -> smem; local sum ----
    float lsum = 0.0f;
    #pragma unroll
    for (int h = 0; h < 2; h++) {
        #pragma unroll
        for (int i = 0; i < HALF_THR; i++) {
            const int off = (h * HALF_THR + i) * THREADS + threadIdx.x;
            float4 x  = __ldcs(p4 + off);
            float4 nz = __ldcs(n4 + off);
            float4 pv = __ldcs(w4 + off);
            float4 np_, wv;
            np_.x = transition_likelihood(x.x, nz.x, cterm, ob, pv.x, wv.x);
            np_.y = transition_likelihood(x.y, nz.y, cterm, ob, pv.y, wv.y);
            np_.z = transition_likelihood(x.z, nz.z, cterm, ob, pv.z, wv.z);
            np_.w = transition_likelihood(x.w, nz.w, cterm, ob, pv.w, wv.w);
            __stcs(onp4 + off, np_);                   // pure streaming output
            w_s[off] = wv;                             // staged in smem
            lsum += (wv.x + wv.y) + (wv.z + wv.w);
        }
    }

    // Block-reduce lsum -> s_partial
    #pragma unroll
    for (int s = 16; s > 0; s >>= 1)
        lsum += __shfl_xor_sync(0xFFFFFFFFu, lsum, s);
    const int lane = threadIdx.x & 31;
    const int wid  = threadIdx.x >> 5;
    if (lane == 0) red[wid] = lsum;
    __syncthreads();
    if (wid == 0) {
        float v = (lane < THREADS / 32) ? red[lane] : 0.0f;
        #pragma unroll
        for (int s = 4; s > 0; s >>= 1)
            v += __shfl_xor_sync(0xFFFFFFFFu, v, s);
        if (lane == 0) s_partial = v;
    }
    __syncthreads();

    // ---- Cluster barrier: all 8 slices' partials published ----
    cluster.sync();

    // ---- Phase 2: row sum via DSMEM, normalize smem slice, stream out ----
    float rsum = 0.0f;
    #pragma unroll
    for (int c = 0; c < CLUSTER; c++) {
        const float* pp = cluster.map_shared_rank(&s_partial, c);
        rsum += *pp;
    }
    const float inv = __frcp_rn(rsum);

    #pragma unroll
    for (int i = 0; i < VEC_PER_THR; i++) {
        const int off = i * THREADS + threadIdx.x;
        float4 wv = w_s[off];
        wv.x *= inv; wv.y *= inv; wv.z *= inv; wv.w *= inv;
        __stcs(ow4 + off, wv);
    }

    // No trailing cluster.sync needed: every CTA reads peers only between the
    // barrier above and its own exit, and DSMEM reads target peers that are
    // still resident (cluster retires as a unit).
    cluster.sync();
}

extern "C" void kernel_launch(void* const* d_in, const int* in_sizes, int n_in,
                              void* d_out, int out_size)
{
    const float* particles = (const float*)d_in[0];   // [B, N, 1]
    const float* pw        = (const float*)d_in[1];   // [B, N]
    const float* obs       = (const float*)d_in[2];   // [B, 1]
    const float* noise     = (const float*)d_in[3];   // [B, N, 1]
    // d_in[4] = uniforms — dead in the reference (resample output unused)
    const int*   tstep     = (const int*)d_in[5];     // scalar

    float* out_np = (float*)d_out;                    // [B, N, 1]
    float* out_w  = out_np + (size_t)B_DIM * N_DIM;   // [B, N]

    cudaFuncSetAttribute(pf_cluster_kernel,
                         cudaFuncAttributeMaxDynamicSharedMemorySize,
                         SMEM_BYTES);

    dim3 grid(CLUSTER, B_DIM);                        // 8 x 128 CTAs, cluster(8,1,1)
    pf_cluster_kernel<<<grid, THREADS, SMEM_BYTES>>>(
        particles, pw, obs, noise, tstep, out_np, out_w);
}